// round 15
// baseline (speedup 1.0000x reference)
#include <cuda_runtime.h>
#include <cuda_bf16.h>
#include <cuda_fp16.h>
#include <cstdint>

#define NN 100000
#define EE 1200000
#define ET (EE + NN)

// ---------------- scratch (static device memory: allocation-free) ----------
__device__ __half g_xwh[NN * 128];   // post-GEMM features, fp16 (gather payload)
__device__ float g_h[NN * 128];      // aggregated layer output (GEMM input, fp32)
__device__ float g_ssrc[NN * 4];
__device__ float g_sdst[NN * 4];
__device__ int   g_cnt[NN];          // zero at load; re-zeroed by k_fill tail
__device__ int   g_off[NN + 1];
__device__ int   g_rank[EE];         // within-node edge rank (from k_count)
__device__ int   g_csr[ET];
__device__ int   g_bsum[128];
__device__ unsigned g_gmaxu[3][4];   // per-layer slots, reset in k_prep
// W images: transposed (B[n][k] = W[k][n]) bf16 hi/lo, padded rows of 272B
#define BSTRIDE 272
#define WIMG (128 * BSTRIDE)
__device__ __align__(16) unsigned char g_Wh[3][WIMG];
__device__ __align__(16) unsigned char g_Wl[3][WIMG];

// ---------------- small helpers ---------------------------------------------
__device__ __forceinline__ unsigned encf(float f) {
    unsigned u = __float_as_uint(f);
    return (u & 0x80000000u) ? ~u : (u | 0x80000000u);
}
__device__ __forceinline__ float decf(unsigned u) {
    return (u & 0x80000000u) ? __uint_as_float(u ^ 0x80000000u) : __uint_as_float(~u);
}
__device__ __forceinline__ uint32_t smem_u32(const void* p) {
    uint32_t a;
    asm("{ .reg .u64 t; cvta.to.shared.u64 t, %1; cvt.u32.u64 %0, t; }"
        : "=r"(a) : "l"(p));
    return a;
}
#define LDSM4(r, a) \
    asm volatile("ldmatrix.sync.aligned.m8n8.x4.shared.b16 {%0,%1,%2,%3},[%4];" \
        : "=r"((r)[0]), "=r"((r)[1]), "=r"((r)[2]), "=r"((r)[3]) : "r"(a))
__device__ __forceinline__ void mma16816(float* c, const uint32_t* a, const uint32_t* b) {
    asm volatile(
        "mma.sync.aligned.m16n8k16.row.col.f32.bf16.bf16.f32 "
        "{%0,%1,%2,%3},{%4,%5,%6,%7},{%8,%9},{%0,%1,%2,%3};"
        : "+f"(c[0]), "+f"(c[1]), "+f"(c[2]), "+f"(c[3])
        : "r"(a[0]), "r"(a[1]), "r"(a[2]), "r"(a[3]), "r"(b[0]), "r"(b[1]));
}
// accumulate 8 halves (uint4) scaled by ex into acc[8]
__device__ __forceinline__ void acc8(float* acc, uint4 q, float ex) {
    float2 p0 = __half22float2(*(__half2*)&q.x);
    float2 p1 = __half22float2(*(__half2*)&q.y);
    float2 p2 = __half22float2(*(__half2*)&q.z);
    float2 p3 = __half22float2(*(__half2*)&q.w);
    acc[0] += ex * p0.x; acc[1] += ex * p0.y;
    acc[2] += ex * p1.x; acc[3] += ex * p1.y;
    acc[4] += ex * p2.x; acc[5] += ex * p2.y;
    acc[6] += ex * p3.x; acc[7] += ex * p3.y;
}

// ---------------- CSR build -------------------------------------------------
__global__ void k_count(const int* __restrict__ ei) {
    int e = blockIdx.x * blockDim.x + threadIdx.x;
    if (e < EE) g_rank[e] = atomicAdd(&g_cnt[ei[EE + e]], 1);
}
__global__ void k_scan1() {
    __shared__ int s[1024];
    int i = blockIdx.x * 1024 + threadIdx.x;
    int v = (i < NN) ? g_cnt[i] : 0;
    s[threadIdx.x] = v;
    __syncthreads();
    for (int d = 1; d < 1024; d <<= 1) {
        int t = (threadIdx.x >= d) ? s[threadIdx.x - d] : 0;
        __syncthreads();
        s[threadIdx.x] += t;
        __syncthreads();
    }
    if (i < NN) g_off[i] = s[threadIdx.x] - v;
    if (threadIdx.x == 1023) g_bsum[blockIdx.x] = s[1023];
}
__global__ void k_scan2() {
    __shared__ int s[128];
    int v = (threadIdx.x < 98) ? g_bsum[threadIdx.x] : 0;
    s[threadIdx.x] = v;
    __syncthreads();
    for (int d = 1; d < 128; d <<= 1) {
        int t = (threadIdx.x >= d) ? s[threadIdx.x - d] : 0;
        __syncthreads();
        s[threadIdx.x] += t;
        __syncthreads();
    }
    g_bsum[threadIdx.x] = s[threadIdx.x] - v;
}
__global__ void k_scan3() {
    int i = blockIdx.x * blockDim.x + threadIdx.x;
    if (i < NN) g_off[i] = g_off[i] + g_bsum[i >> 10] + i;  // +i folds self-loops
    if (i == 0) g_off[NN] = ET;
}
__global__ void k_fill(const int* __restrict__ ei) {
    int e = blockIdx.x * blockDim.x + threadIdx.x;
    if (e < EE) {
        int d = ei[EE + e];
        g_csr[g_off[d] + g_rank[e]] = ei[e];   // atomic-free via precomputed rank
    } else if (e < ET) {
        int v = e - EE;
        g_csr[g_off[v + 1] - 1] = v;           // self-loop in the last slot
        g_cnt[v] = 0;                          // reset for next call
    }
}

// ---------------- W prep: transpose + bf16 hi/lo split + gmax reset --------
__global__ void k_prep(const float* __restrict__ W1, const float* __restrict__ W2,
                       const float* __restrict__ W3) {
    int t = blockIdx.x * 256 + threadIdx.x;
    if (t < 12) ((unsigned*)g_gmaxu)[t] = 0u;
    if (t >= 3 * 16384) return;
    int layer = t >> 14;
    int r = t & 16383;
    int n = r >> 7, k = r & 127;  // B[n][k] = W[k][n]
    const float* W = (layer == 0) ? W1 : (layer == 1) ? W2 : W3;
    float v = W[k * 128 + n];
    __nv_bfloat16 h = __float2bfloat16(v);
    __nv_bfloat16 l = __float2bfloat16(v - __bfloat162float(h));
    unsigned off = n * BSTRIDE + k * 2;
    *(__nv_bfloat16*)(g_Wh[layer] + off) = h;
    *(__nv_bfloat16*)(g_Wl[layer] + off) = l;
}

// ---------------- HMMA split-bf16 GEMM + fused scores + fused gmax ---------
#define OFF_BH 0
#define OFF_BL 34816
#define OFF_AH 69632
#define OFF_AL 104448
#define OFF_AS 139264
#define OFF_AD 139776
#define OFF_GM 140288
#define SMEM_TOT 140352

__global__ void __launch_bounds__(256, 1)
k_mm(const float* __restrict__ Xext,
     const float* __restrict__ asrc, const float* __restrict__ adst, int layer) {
    extern __shared__ __align__(16) unsigned char smem[];
    uint32_t sb = smem_u32(smem);
    int tid = threadIdx.x;
    int w = tid >> 5, lane = tid & 31;
    const float* X = layer ? (const float*)g_h : Xext;
    int row0 = blockIdx.x * 128;
    unsigned* sGM = (unsigned*)(smem + OFF_GM);

    if (tid < 4) sGM[tid] = 0u;
    {
        const uint4* srcH = (const uint4*)g_Wh[layer];
        const uint4* srcL = (const uint4*)g_Wl[layer];
        uint4* dH = (uint4*)(smem + OFF_BH);
        uint4* dL = (uint4*)(smem + OFF_BL);
        for (int i = tid; i < 2176; i += 256) {
            dH[i] = srcH[i];
            dL[i] = srcL[i];
        }
    }
    if (tid < 128) {
        ((float*)(smem + OFF_AS))[tid] = asrc[tid];
        ((float*)(smem + OFF_AD))[tid] = adst[tid];
    }
    for (int t = tid; t < 2048; t += 256) {
        int mrow = t >> 4, k0 = (t & 15) << 3;
        int gr = row0 + mrow;
        float4 v0 = make_float4(0.f, 0.f, 0.f, 0.f), v1 = v0;
        if (gr < NN) {
            v0 = ((const float4*)X)[gr * 32 + (k0 >> 2)];
            v1 = ((const float4*)X)[gr * 32 + (k0 >> 2) + 1];
        }
        float f[8] = {v0.x, v0.y, v0.z, v0.w, v1.x, v1.y, v1.z, v1.w};
        __nv_bfloat162 hi[4], lo[4];
#pragma unroll
        for (int j = 0; j < 4; j++) {
            __nv_bfloat16 h0 = __float2bfloat16(f[2 * j]);
            __nv_bfloat16 h1 = __float2bfloat16(f[2 * j + 1]);
            hi[j] = __nv_bfloat162(h0, h1);
            lo[j] = __nv_bfloat162(
                __float2bfloat16(f[2 * j] - __bfloat162float(h0)),
                __float2bfloat16(f[2 * j + 1] - __bfloat162float(h1)));
        }
        unsigned off = mrow * BSTRIDE + k0 * 2;
        *(uint4*)(smem + OFF_AH + off) = *(uint4*)hi;
        *(uint4*)(smem + OFF_AL + off) = *(uint4*)lo;
    }
    __syncthreads();

    int lrow = lane & 7, lmat = lane >> 3;
    uint32_t aoff = (uint32_t)(((lmat & 1) * 8 + lrow) * BSTRIDE + (lmat >> 1) * 16);
    uint32_t boff = (uint32_t)(lrow * BSTRIDE + ((lane >> 3) & 1) * 16 +
                               (lane >> 4) * (8 * BSTRIDE));
    uint32_t aHa = sb + OFF_AH + w * 16 * BSTRIDE + aoff;
    uint32_t aLa = sb + OFF_AL + w * 16 * BSTRIDE + aoff;

    uint32_t ah[8][4], al[8][4];
#pragma unroll
    for (int s = 0; s < 8; s++) {
        LDSM4(ah[s], aHa + s * 32);
        LDSM4(al[s], aLa + s * 32);
    }

    float acc[16][4];
#pragma unroll
    for (int nt = 0; nt < 16; nt++) {
        acc[nt][0] = 0.f; acc[nt][1] = 0.f; acc[nt][2] = 0.f; acc[nt][3] = 0.f;
    }

    uint32_t bH = sb + OFF_BH + boff;
    uint32_t bL = sb + OFF_BL + boff;
#pragma unroll
    for (int p = 0; p < 8; p++) {
        uint32_t ofs = p * (16 * BSTRIDE);
#pragma unroll
        for (int s = 0; s < 8; s++) {
            uint32_t b4[4];
            LDSM4(b4, bH + ofs + s * 32);
            mma16816(acc[2 * p],     ah[s], b4);
            mma16816(acc[2 * p + 1], ah[s], b4 + 2);
            mma16816(acc[2 * p],     al[s], b4);
            mma16816(acc[2 * p + 1], al[s], b4 + 2);
        }
#pragma unroll
        for (int s = 0; s < 8; s++) {
            uint32_t b4[4];
            LDSM4(b4, bL + ofs + s * 32);
            mma16816(acc[2 * p],     ah[s], b4);
            mma16816(acc[2 * p + 1], ah[s], b4 + 2);
        }
    }

    const float* sAS = (const float*)(smem + OFF_AS);
    const float* sAD = (const float*)(smem + OFF_AD);
    int rbase = row0 + w * 16 + (lane >> 2);
#pragma unroll
    for (int rr = 0; rr < 2; rr++) {
        int m = rbase + rr * 8;
        float pss[4] = {0.f, 0.f, 0.f, 0.f};
        float pdd[4] = {0.f, 0.f, 0.f, 0.f};
#pragma unroll
        for (int nt = 0; nt < 16; nt++) {
            float c0 = acc[nt][rr * 2 + 0], c1 = acc[nt][rr * 2 + 1];
            int col = nt * 8 + (lane & 3) * 2;
            pss[nt >> 2] += c0 * sAS[col] + c1 * sAS[col + 1];
            pdd[nt >> 2] += c0 * sAD[col] + c1 * sAD[col + 1];
            if (m < NN) {
                __half2 hp = __floats2half2_rn(c0, c1);
                *(unsigned*)&g_xwh[m * 128 + col] = *(unsigned*)&hp;
            }
        }
        float mysrc = 0.f, mydst = 0.f;
#pragma unroll
        for (int j = 0; j < 4; j++) {
            float t = pss[j];
            t += __shfl_xor_sync(0xffffffffu, t, 1);
            t += __shfl_xor_sync(0xffffffffu, t, 2);
            if ((lane & 3) == j) mysrc = t;
            t = pdd[j];
            t += __shfl_xor_sync(0xffffffffu, t, 1);
            t += __shfl_xor_sync(0xffffffffu, t, 2);
            if ((lane & 3) == j) mydst = t;
        }
        if (m < NN) {
            g_ssrc[m * 4 + (lane & 3)] = mysrc;
            g_sdst[m * 4 + (lane & 3)] = mydst;
            atomicMax(&sGM[lane & 3], encf(mysrc));
        }
    }
    __syncthreads();
    if (tid < 4) atomicMax(&g_gmaxu[layer][tid], sGM[tid]);
}

// ---------------- warp-per-node aggregation, 2 edges/iter (half-warps) -----
// mh = max(0, gmax_h + s_dst[v,h]) >= leaky(s_src[u]+s_dst[v]); shift-invariant.
// Lane l: half = l>>4 (edge slot), li = l&15 covers cols [8li, 8li+8), head li>>2.
template <bool LAST>
__global__ void k_agg(const float* __restrict__ bias, float* __restrict__ outp,
                      int layer) {
    int g = blockIdx.x * blockDim.x + threadIdx.x;
    int v = g >> 5, lane = g & 31;
    if (v >= NN) return;
    int half = lane >> 4, li = lane & 15;
    int offv = g_off[v];
    int deg = g_off[v + 1] - offv;
    int hh = li >> 2;
    float sd = g_sdst[v * 4 + hh];
    float mh = fmaxf(decf(g_gmaxu[layer][hh]) + sd, 0.f);

    const uint4* XW = (const uint4*)g_xwh;  // 16 slots of 8 halves per node

    float acc[8] = {0.f, 0.f, 0.f, 0.f, 0.f, 0.f, 0.f, 0.f};
    float dsum = 0.f;
    int e = 0;
    for (; e + 4 <= deg; e += 4) {  // 4 edges per iteration (2 per half-warp)
        int u0 = g_csr[offv + e + half];
        int u1 = g_csr[offv + e + 2 + half];
        float a0 = g_ssrc[u0 * 4 + hh] + sd;
        float a1 = g_ssrc[u1 * 4 + hh] + sd;
        uint4 q0 = XW[u0 * 16 + li];
        uint4 q1 = XW[u1 * 16 + li];
        a0 = (a0 > 0.f) ? a0 : 0.2f * a0;
        a1 = (a1 > 0.f) ? a1 : 0.2f * a1;
        float e0 = __expf(a0 - mh);
        float e1 = __expf(a1 - mh);
        dsum += e0 + e1;
        acc8(acc, q0, e0);
        acc8(acc, q1, e1);
    }
    for (; e < deg; e += 2) {  // tail: up to 2 edges per iteration
        int idx = e + half;
        if (idx < deg) {
            int u = g_csr[offv + idx];
            float a = g_ssrc[u * 4 + hh] + sd;
            uint4 q = XW[u * 16 + li];
            a = (a > 0.f) ? a : 0.2f * a;
            float ex = __expf(a - mh);
            dsum += ex;
            acc8(acc, q, ex);
        }
    }

    // cross-half reduction (both halves end with full sums)
#pragma unroll
    for (int i = 0; i < 8; i++) acc[i] += __shfl_xor_sync(0xffffffffu, acc[i], 16);
    dsum += __shfl_xor_sync(0xffffffffu, dsum, 16);
    float inv = 1.f / dsum;
#pragma unroll
    for (int i = 0; i < 8; i++) acc[i] *= inv;

    if (!LAST) {
        if (half == 0) {
            float4 b0 = ((const float4*)bias)[li * 2];
            float4 b1 = ((const float4*)bias)[li * 2 + 1];
            float o[8] = {acc[0] + b0.x, acc[1] + b0.y, acc[2] + b0.z, acc[3] + b0.w,
                          acc[4] + b1.x, acc[5] + b1.y, acc[6] + b1.z, acc[7] + b1.w};
#pragma unroll
            for (int i = 0; i < 8; i++) o[i] = o[i] > 0.f ? o[i] : expm1f(o[i]);
            ((float4*)g_h)[v * 32 + li * 2] = make_float4(o[0], o[1], o[2], o[3]);
            ((float4*)g_h)[v * 32 + li * 2 + 1] = make_float4(o[4], o[5], o[6], o[7]);
        }
    } else {
        // mean over heads: lanes li, li+4, li+8, li+12 hold same within-head cols
#pragma unroll
        for (int i = 0; i < 8; i++) {
            acc[i] += __shfl_xor_sync(0xffffffffu, acc[i], 4);
            acc[i] += __shfl_xor_sync(0xffffffffu, acc[i], 8);
        }
        if (half == 0 && li < 4) {
            float4 b0 = ((const float4*)bias)[li * 2];
            float4 b1 = ((const float4*)bias)[li * 2 + 1];
            ((float4*)outp)[v * 8 + li * 2] =
                make_float4(acc[0] * 0.25f + b0.x, acc[1] * 0.25f + b0.y,
                            acc[2] * 0.25f + b0.z, acc[3] * 0.25f + b0.w);
            ((float4*)outp)[v * 8 + li * 2 + 1] =
                make_float4(acc[4] * 0.25f + b1.x, acc[5] * 0.25f + b1.y,
                            acc[6] * 0.25f + b1.z, acc[7] * 0.25f + b1.w);
        }
    }
}

// ---------------- driver ----------------------------------------------------
extern "C" void kernel_launch(void* const* d_in, const int* in_sizes, int n_in,
                              void* d_out, int out_size) {
    const float* x   = (const float*)d_in[0];
    const int*   ei  = (const int*)d_in[1];
    const float* W1  = (const float*)d_in[2];
    const float* as1 = (const float*)d_in[3];
    const float* ad1 = (const float*)d_in[4];
    const float* b1  = (const float*)d_in[5];
    const float* W2  = (const float*)d_in[6];
    const float* as2 = (const float*)d_in[7];
    const float* ad2 = (const float*)d_in[8];
    const float* b2  = (const float*)d_in[9];
    const float* W3  = (const float*)d_in[10];
    const float* as3 = (const float*)d_in[11];
    const float* ad3 = (const float*)d_in[12];
    const float* b3  = (const float*)d_in[13];
    float* out = (float*)d_out;

    cudaFuncSetAttribute(k_mm, cudaFuncAttributeMaxDynamicSharedMemorySize, SMEM_TOT);

    const int MB = (NN + 127) / 128;  // 782
    const int WB = NN / 8;            // 12500 blocks, warp per node

    // fork the CSR build onto a side stream; join before k_agg(L1)
    cudaStream_t s2;
    cudaStreamCreateWithFlags(&s2, cudaStreamNonBlocking);
    cudaEvent_t evF, evJ;
    cudaEventCreateWithFlags(&evF, cudaEventDisableTiming);
    cudaEventCreateWithFlags(&evJ, cudaEventDisableTiming);

    cudaEventRecord(evF, 0);
    cudaStreamWaitEvent(s2, evF, 0);
    k_count<<<(EE + 255) / 256, 256, 0, s2>>>(ei);
    k_scan1<<<98, 1024, 0, s2>>>();
    k_scan2<<<1, 128, 0, s2>>>();
    k_scan3<<<(NN + 255) / 256, 256, 0, s2>>>();
    k_fill<<<(ET + 255) / 256, 256, 0, s2>>>(ei);
    cudaEventRecord(evJ, s2);

    // main branch: weight prep + layer-1 GEMM in parallel with CSR
    k_prep<<<192, 256>>>(W1, W2, W3);
    k_mm<<<MB, 256, SMEM_TOT>>>(x, as1, ad1, 0);
    cudaStreamWaitEvent(0, evJ, 0);

    k_agg<false><<<WB, 256>>>(b1, nullptr, 0);

    k_mm<<<MB, 256, SMEM_TOT>>>(nullptr, as2, ad2, 1);
    k_agg<false><<<WB, 256>>>(b2, nullptr, 1);

    k_mm<<<MB, 256, SMEM_TOT>>>(nullptr, as3, ad3, 2);
    k_agg<true><<<WB, 256>>>(b3, out, 2);
}